// round 4
// baseline (speedup 1.0000x reference)
#include <cuda_runtime.h>
#include <cstdint>

// Problem constants (from reference)
#define BDIM      256      // threads per block (8 warps)
#define D_F4      64       // CODE_DIM / 4 = 256/4 float4 per sample
#define K_CENT    4
#define N_CLASSES 1000

// Warp-per-sample: lane l holds codes[4l..4l+3] and codes[4(l+32)..4(l+32)+3].
// 4 accumulators (one per centroid), codes read once from DRAM, centroids from L2.
__global__ void __launch_bounds__(BDIM) sparse_codebook_kernel(
    const float4* __restrict__ codes,      // [B, 64] float4
    const int* __restrict__ pred,          // [B]  (int32 — JAX x64-disabled demotes int64)
    const float4* __restrict__ cents,      // [1000, 4, 64] float4
    float* __restrict__ out,               // [B]
    int B)
{
    const int warp_global = (int)((blockIdx.x * (unsigned)BDIM + threadIdx.x) >> 5);
    const int lane = threadIdx.x & 31;
    if (warp_global >= B) return;

    // --- load this sample's codes (coalesced, 2x float4 per lane) ---
    const float4* __restrict__ c = codes + (size_t)warp_global * D_F4;
    const float4 a0 = __ldg(&c[lane]);
    const float4 a1 = __ldg(&c[lane + 32]);

    // --- class index (uniform across warp -> broadcast load); clamp defensively ---
    int cls = __ldg(&pred[warp_global]);
    cls = min(max(cls, 0), N_CLASSES - 1);
    const float4* __restrict__ ct = cents + (size_t)cls * (K_CENT * D_F4);

    float s0 = 0.f, s1 = 0.f, s2 = 0.f, s3 = 0.f;

    {
        float4 b0 = __ldg(&ct[0 * D_F4 + lane]);
        float4 b1 = __ldg(&ct[0 * D_F4 + lane + 32]);
        s0 += fabsf(a0.x - b0.x) + fabsf(a0.y - b0.y) + fabsf(a0.z - b0.z) + fabsf(a0.w - b0.w)
            + fabsf(a1.x - b1.x) + fabsf(a1.y - b1.y) + fabsf(a1.z - b1.z) + fabsf(a1.w - b1.w);
    }
    {
        float4 b0 = __ldg(&ct[1 * D_F4 + lane]);
        float4 b1 = __ldg(&ct[1 * D_F4 + lane + 32]);
        s1 += fabsf(a0.x - b0.x) + fabsf(a0.y - b0.y) + fabsf(a0.z - b0.z) + fabsf(a0.w - b0.w)
            + fabsf(a1.x - b1.x) + fabsf(a1.y - b1.y) + fabsf(a1.z - b1.z) + fabsf(a1.w - b1.w);
    }
    {
        float4 b0 = __ldg(&ct[2 * D_F4 + lane]);
        float4 b1 = __ldg(&ct[2 * D_F4 + lane + 32]);
        s2 += fabsf(a0.x - b0.x) + fabsf(a0.y - b0.y) + fabsf(a0.z - b0.z) + fabsf(a0.w - b0.w)
            + fabsf(a1.x - b1.x) + fabsf(a1.y - b1.y) + fabsf(a1.z - b1.z) + fabsf(a1.w - b1.w);
    }
    {
        float4 b0 = __ldg(&ct[3 * D_F4 + lane]);
        float4 b1 = __ldg(&ct[3 * D_F4 + lane + 32]);
        s3 += fabsf(a0.x - b0.x) + fabsf(a0.y - b0.y) + fabsf(a0.z - b0.z) + fabsf(a0.w - b0.w)
            + fabsf(a1.x - b1.x) + fabsf(a1.y - b1.y) + fabsf(a1.z - b1.z) + fabsf(a1.w - b1.w);
    }

    // --- warp butterfly reduce all 4 sums ---
    #pragma unroll
    for (int off = 16; off > 0; off >>= 1) {
        s0 += __shfl_xor_sync(0xFFFFFFFFu, s0, off);
        s1 += __shfl_xor_sync(0xFFFFFFFFu, s1, off);
        s2 += __shfl_xor_sync(0xFFFFFFFFu, s2, off);
        s3 += __shfl_xor_sync(0xFFFFFFFFu, s3, off);
    }

    if (lane == 0) {
        float m = fminf(fminf(s0, s1), fminf(s2, s3));
        out[warp_global] = m * (1.0f / 256.0f);
    }
}

extern "C" void kernel_launch(void* const* d_in, const int* in_sizes, int n_in,
                              void* d_out, int out_size)
{
    // Identify inputs by element count (robust to metadata ordering):
    //   codes:     B * 256    = 67,108,864  (largest)
    //   centroids: 1000*4*256 = 1,024,000   (middle)
    //   pred:      B          = 262,144     (smallest)
    int i_codes = 0, i_pred = 0, i_cent = 0;
    for (int i = 1; i < n_in; ++i) {
        if (in_sizes[i] > in_sizes[i_codes]) i_codes = i;
        if (in_sizes[i] < in_sizes[i_pred])  i_pred  = i;
    }
    for (int i = 0; i < n_in; ++i)
        if (i != i_codes && i != i_pred) { i_cent = i; break; }

    const float4* codes = (const float4*)d_in[i_codes];
    const int*    pred  = (const int*)d_in[i_pred];
    const float4* cents = (const float4*)d_in[i_cent];
    float*        out   = (float*)d_out;

    const int B = in_sizes[i_pred];      // element count of pred_class = B
    const int warps_per_block = BDIM / 32;
    const int grid = (B + warps_per_block - 1) / warps_per_block;

    sparse_codebook_kernel<<<grid, BDIM>>>(codes, pred, cents, out, B);
}